// round 1
// baseline (speedup 1.0000x reference)
#include <cuda_runtime.h>
#include <cuda_bf16.h>

#define FULL_MASK 0xFFFFFFFFu

// pair(i,j) with i<=j, nv=5 -> linear index in s[15]
// row offsets: i=0:0, i=1:5, i=2:9, i=3:12, i=4:14
__device__ __forceinline__ constexpr int sidx(int i, int j) {
    // assumes i <= j
    return (i == 0 ? 0 : i == 1 ? 5 : i == 2 ? 9 : i == 3 ? 12 : 14) + (j - i);
}

__global__ void __launch_bounds__(256)
cm_validator_kernel(const float* __restrict__ verts,
                    float* __restrict__ out_pairs,   // (B, 10)
                    float* __restrict__ out_vol,     // (B,)
                    int B)
{
    const int warps_per_block = blockDim.x >> 5;
    const int warp = blockIdx.x * warps_per_block + (threadIdx.x >> 5);
    const int lane = threadIdx.x & 31;
    if (warp >= B) return;

    // Each batch: 5 vertices x 128 floats = 640 floats, contiguous.
    const float4* vp = reinterpret_cast<const float4*>(verts + (size_t)warp * 640);

    // Each lane loads one float4 chunk (4 dims) of each of the 5 vertices.
    float4 v[5];
#pragma unroll
    for (int i = 0; i < 5; i++) {
        v[i] = __ldcs(vp + i * 32 + lane);
    }

    // 15 partial dot products (i<=j) over this lane's 4 dims.
    float s[15];
    {
        int t = 0;
#pragma unroll
        for (int i = 0; i < 5; i++) {
#pragma unroll
            for (int j = i; j < 5; j++) {
                float acc = v[i].x * v[j].x;
                acc = fmaf(v[i].y, v[j].y, acc);
                acc = fmaf(v[i].z, v[j].z, acc);
                acc = fmaf(v[i].w, v[j].w, acc);
                s[t++] = acc;
            }
        }
    }

    // Butterfly reduce all 15 sums across the warp (5 rounds x 15 shfl).
#pragma unroll
    for (int m = 16; m > 0; m >>= 1) {
#pragma unroll
        for (int p = 0; p < 15; p++) {
            s[p] += __shfl_xor_sync(FULL_MASK, s[p], m);
        }
    }

    // Squared distances: d2(i,j) = relu(n_i + n_j - 2*g_ij); diagonal exactly 0.
    float D[5][5];
#pragma unroll
    for (int i = 0; i < 5; i++) {
#pragma unroll
        for (int j = 0; j < 5; j++) {
            if (i == j) {
                D[i][j] = 0.0f;
            } else {
                const int lo = i < j ? i : j;
                const int hi = i < j ? j : i;
                const float g = s[sidx(lo, hi)];
                const float ni = s[sidx(i, i)];
                const float nj = s[sidx(j, j)];
                D[i][j] = fmaxf(ni + nj - 2.0f * g, 0.0f);
            }
        }
    }

    // Cayley-Menger determinant reduced exactly (two unit-pivot eliminations)
    // to a 4x4:  P[a][b] = D[a+1][b+1] - D[0][b+1] - D[a+1][0]
    // det(CM) = -det(P)  =>  vol2 = PREFACTOR * det(CM) = det(P) / 9216.
    float P[4][4];
#pragma unroll
    for (int a = 0; a < 4; a++) {
#pragma unroll
        for (int b = 0; b < 4; b++) {
            P[a][b] = D[a + 1][b + 1] - D[0][b + 1] - D[a + 1][0];
        }
    }

    // 4x4 determinant via 2x2-minor Laplace expansion (rows 0,1 vs rows 2,3).
    const float s0 = P[0][0] * P[1][1] - P[0][1] * P[1][0];
    const float s1 = P[0][0] * P[1][2] - P[0][2] * P[1][0];
    const float s2 = P[0][0] * P[1][3] - P[0][3] * P[1][0];
    const float s3 = P[0][1] * P[1][2] - P[0][2] * P[1][1];
    const float s4 = P[0][1] * P[1][3] - P[0][3] * P[1][1];
    const float s5 = P[0][2] * P[1][3] - P[0][3] * P[1][2];

    const float c0 = P[2][0] * P[3][1] - P[2][1] * P[3][0];
    const float c1 = P[2][0] * P[3][2] - P[2][2] * P[3][0];
    const float c2 = P[2][0] * P[3][3] - P[2][3] * P[3][0];
    const float c3 = P[2][1] * P[3][2] - P[2][2] * P[3][1];
    const float c4 = P[2][1] * P[3][3] - P[2][3] * P[3][1];
    const float c5 = P[2][2] * P[3][3] - P[2][3] * P[3][2];

    const float det4 = s0 * c5 - s1 * c4 + s2 * c3 + s3 * c2 - s4 * c1 + s5 * c0;
    const float vol2 = det4 * (1.0f / 9216.0f);

    // Pair values in reference order:
    // (0,1),(0,2),(0,3),(0,4),(1,2),(1,3),(1,4),(2,3),(2,4),(3,4)
    float pv = 0.0f;
    {
        int p = 0;
#pragma unroll
        for (int i = 0; i < 5; i++) {
#pragma unroll
            for (int j = i + 1; j < 5; j++) {
                pv = (lane == p) ? D[i][j] : pv;
                p++;
            }
        }
    }

    if (lane < 10) {
        out_pairs[(size_t)warp * 10 + lane] = pv;
    }
    if (lane == 0) {
        out_vol[warp] = vol2;
    }
}

extern "C" void kernel_launch(void* const* d_in, const int* in_sizes, int n_in,
                              void* d_out, int out_size) {
    const float* verts = (const float*)d_in[0];
    const int B = in_sizes[0] / 640;   // (B, 5, 128) float32

    float* out = (float*)d_out;
    float* out_pairs = out;                      // (B, 10) flattened first
    float* out_vol   = out + (size_t)B * 10;     // (B,) concatenated after

    const int warps_per_block = 8;               // 256 threads
    const int blocks = (B + warps_per_block - 1) / warps_per_block;
    cm_validator_kernel<<<blocks, 256>>>(verts, out_pairs, out_vol, B);
}

// round 3
// speedup vs baseline: 1.1219x; 1.1219x over previous
#include <cuda_runtime.h>
#include <cuda_bf16.h>

#define FULL_MASK 0xFFFFFFFFu

// gram index for (i,j), i<=j, nv=5 -> linear index in s[15]
__device__ __forceinline__ constexpr int sidx(int i, int j) {
    return (i == 0 ? 0 : i == 1 ? 5 : i == 2 ? 9 : i == 3 ? 12 : 14) + (j - i);
}

// pair index for (i,j), i<j, nv=5 -> 0..9 in reference order
__device__ __forceinline__ constexpr int pidx(int i, int j) {
    return (i == 0 ? 0 : i == 1 ? 3 : i == 2 ? 5 : 6) + (j - 1);
}

__global__ void __launch_bounds__(256)
cm_validator_kernel(const float* __restrict__ verts,
                    float* __restrict__ out_pairs,   // (B, 10)
                    float* __restrict__ out_vol,     // (B,)
                    int B)
{
    const int warp = blockIdx.x * (blockDim.x >> 5) + (threadIdx.x >> 5);
    const int lane = threadIdx.x & 31;
    const int half = lane >> 4;        // which batch within the warp
    const int sub  = lane & 15;        // 16 lanes x 8 dims per batch
    const int batch = warp * 2 + half;
    if (batch >= B) return;

    // Batch layout: 5 vertices x 128 floats contiguous = 160 float4.
    // Lane covers dims [sub*8, sub*8+8) = float4 chunks {2*sub, 2*sub+1}.
    const float4* vp = reinterpret_cast<const float4*>(verts)
                       + (size_t)batch * 160 + sub * 2;

    float4 v[5][2];
#pragma unroll
    for (int i = 0; i < 5; i++) {
#pragma unroll
        for (int c = 0; c < 2; c++) {
            v[i][c] = __ldcs(vp + i * 32 + c);
        }
    }

    // 15 partial dot products (i<=j) over this lane's 8 dims.
    float s[15];
    {
        int t = 0;
#pragma unroll
        for (int i = 0; i < 5; i++) {
#pragma unroll
            for (int j = i; j < 5; j++) {
                float acc = v[i][0].x * v[j][0].x;
                acc = fmaf(v[i][0].y, v[j][0].y, acc);
                acc = fmaf(v[i][0].z, v[j][0].z, acc);
                acc = fmaf(v[i][0].w, v[j][0].w, acc);
                acc = fmaf(v[i][1].x, v[j][1].x, acc);
                acc = fmaf(v[i][1].y, v[j][1].y, acc);
                acc = fmaf(v[i][1].z, v[j][1].z, acc);
                acc = fmaf(v[i][1].w, v[j][1].w, acc);
                s[t++] = acc;
            }
        }
    }

    // Butterfly all-reduce within each half-warp: 4 rounds x 15 shfl.
#pragma unroll
    for (int m = 8; m > 0; m >>= 1) {
#pragma unroll
        for (int p = 0; p < 15; p++) {
            s[p] += __shfl_xor_sync(FULL_MASK, s[p], m);
        }
    }

    // Squared distances for the 10 pairs (upper triangle), reference order.
    float n0 = s[sidx(0,0)], n1 = s[sidx(1,1)], n2 = s[sidx(2,2)],
          n3 = s[sidx(3,3)], n4 = s[sidx(4,4)];
    float nrm[5] = {n0, n1, n2, n3, n4};

    float d2[10];
    {
#pragma unroll
        for (int i = 0; i < 5; i++) {
#pragma unroll
            for (int j = i + 1; j < 5; j++) {
                const float g = s[sidx(i, j)];
                d2[pidx(i, j)] = fmaxf(fmaf(-2.0f, g, nrm[i] + nrm[j]), 0.0f);
            }
        }
    }

    // Cayley-Menger determinant reduced exactly (two unit-pivot eliminations)
    // to a symmetric 4x4:  P[a][b] = D[a+1][b+1] - D[0][b+1] - D[0][a+1]
    // vol2 = PREFACTOR * det(CM) = det(P) / 9216.
    const float p00 = -2.0f * d2[pidx(0,1)];
    const float p11 = -2.0f * d2[pidx(0,2)];
    const float p22 = -2.0f * d2[pidx(0,3)];
    const float p33 = -2.0f * d2[pidx(0,4)];
    const float p01 = d2[pidx(1,2)] - d2[pidx(0,2)] - d2[pidx(0,1)];
    const float p02 = d2[pidx(1,3)] - d2[pidx(0,3)] - d2[pidx(0,1)];
    const float p03 = d2[pidx(1,4)] - d2[pidx(0,4)] - d2[pidx(0,1)];
    const float p12 = d2[pidx(2,3)] - d2[pidx(0,3)] - d2[pidx(0,2)];
    const float p13 = d2[pidx(2,4)] - d2[pidx(0,4)] - d2[pidx(0,2)];
    const float p23 = d2[pidx(3,4)] - d2[pidx(0,4)] - d2[pidx(0,3)];

    // det of symmetric 4x4 via 2x2 minors (rows 0,1 vs rows 2,3); c0 == s5.
    const float s0 = p00 * p11 - p01 * p01;
    const float s1 = p00 * p12 - p02 * p01;
    const float s2 = p00 * p13 - p03 * p01;
    const float s3 = p01 * p12 - p02 * p11;
    const float s4 = p01 * p13 - p03 * p11;
    const float s5 = p02 * p13 - p03 * p12;

    const float c1 = p02 * p23 - p22 * p03;
    const float c2 = p02 * p33 - p23 * p03;
    const float c3 = p12 * p23 - p22 * p13;
    const float c4 = p12 * p33 - p23 * p13;
    const float c5 = p22 * p33 - p23 * p23;

    const float det4 = s0 * c5 - s1 * c4 + s2 * c3 + s3 * c2 - s4 * c1 + s5 * s5;
    const float vol2 = det4 * (1.0f / 9216.0f);

    // Select this lane's pair value (lanes sub=0..9 own pairs 0..9).
    float pv = d2[0];
    pv = (sub == 1) ? d2[1] : pv;
    pv = (sub == 2) ? d2[2] : pv;
    pv = (sub == 3) ? d2[3] : pv;
    pv = (sub == 4) ? d2[4] : pv;
    pv = (sub == 5) ? d2[5] : pv;
    pv = (sub == 6) ? d2[6] : pv;
    pv = (sub == 7) ? d2[7] : pv;
    pv = (sub == 8) ? d2[8] : pv;
    pv = (sub == 9) ? d2[9] : pv;

    if (sub < 10) {
        out_pairs[(size_t)batch * 10 + sub] = pv;
    }
    if (sub == 0) {
        out_vol[batch] = vol2;
    }
}

extern "C" void kernel_launch(void* const* d_in, const int* in_sizes, int n_in,
                              void* d_out, int out_size) {
    const float* verts = (const float*)d_in[0];
    const int B = in_sizes[0] / 640;   // (B, 5, 128) float32

    float* out = (float*)d_out;
    float* out_pairs = out;                      // (B, 10) flattened first
    float* out_vol   = out + (size_t)B * 10;     // (B,) concatenated after

    const int warps_needed = (B + 1) / 2;        // 2 batches per warp
    const int warps_per_block = 8;               // 256 threads
    const int blocks = (warps_needed + warps_per_block - 1) / warps_per_block;
    cm_validator_kernel<<<blocks, 256>>>(verts, out_pairs, out_vol, B);
}

// round 4
// speedup vs baseline: 1.1407x; 1.0168x over previous
#include <cuda_runtime.h>
#include <cuda_bf16.h>

#define FULL_MASK 0xFFFFFFFFu

// gram index for (i,j), i<=j, nv=5 -> linear index in s[15]
__device__ __forceinline__ constexpr int sidx(int i, int j) {
    return (i == 0 ? 0 : i == 1 ? 5 : i == 2 ? 9 : i == 3 ? 12 : 14) + (j - i);
}

// pair index for (i,j), i<j, nv=5 -> 0..9 in reference order
__device__ __forceinline__ constexpr int pidx(int i, int j) {
    return (i == 0 ? 0 : i == 1 ? 3 : i == 2 ? 5 : 6) + (j - 1);
}

__global__ void __launch_bounds__(256, 2)
cm_validator_kernel(const float* __restrict__ verts,
                    float* __restrict__ out_pairs,   // (B, 10)
                    float* __restrict__ out_vol,     // (B,)
                    int B)
{
    const int warp = blockIdx.x * (blockDim.x >> 5) + (threadIdx.x >> 5);
    const int lane = threadIdx.x & 31;
    const int grp  = lane >> 3;        // 4 batches per warp
    const int sub  = lane & 7;         // 8 lanes x 16 dims per batch
    const int batch = warp * 4 + grp;
    if (batch >= B) return;

    // Batch layout: 5 vertices x 128 floats contiguous = 160 float4.
    // Lane covers float4 chunks {sub + 8c : c=0..3} of each vertex row, so
    // for each (vertex, chunk) the 8 lanes of a group touch one contiguous
    // 128B segment.
    const float4* vp = reinterpret_cast<const float4*>(verts)
                       + (size_t)batch * 160 + sub;

    float4 v[5][4];
#pragma unroll
    for (int i = 0; i < 5; i++) {
#pragma unroll
        for (int c = 0; c < 4; c++) {
            v[i][c] = __ldcs(vp + i * 32 + c * 8);
        }
    }

    // 15 partial dot products (i<=j) over this lane's 16 dims.
    float s[15];
    {
        int t = 0;
#pragma unroll
        for (int i = 0; i < 5; i++) {
#pragma unroll
            for (int j = i; j < 5; j++) {
                float acc = v[i][0].x * v[j][0].x;
#pragma unroll
                for (int c = 0; c < 4; c++) {
                    if (c > 0) acc = fmaf(v[i][c].x, v[j][c].x, acc);
                    acc = fmaf(v[i][c].y, v[j][c].y, acc);
                    acc = fmaf(v[i][c].z, v[j][c].z, acc);
                    acc = fmaf(v[i][c].w, v[j][c].w, acc);
                }
                s[t++] = acc;
            }
        }
    }

    // Butterfly all-reduce within each 8-lane group: 3 rounds x 15 shfl.
#pragma unroll
    for (int m = 4; m > 0; m >>= 1) {
#pragma unroll
        for (int p = 0; p < 15; p++) {
            s[p] += __shfl_xor_sync(FULL_MASK, s[p], m);
        }
    }

    // Squared distances for the 10 pairs (upper triangle), reference order.
    float nrm[5] = {s[sidx(0,0)], s[sidx(1,1)], s[sidx(2,2)],
                    s[sidx(3,3)], s[sidx(4,4)]};

    float d2[10];
#pragma unroll
    for (int i = 0; i < 5; i++) {
#pragma unroll
        for (int j = i + 1; j < 5; j++) {
            const float g = s[sidx(i, j)];
            d2[pidx(i, j)] = fmaxf(fmaf(-2.0f, g, nrm[i] + nrm[j]), 0.0f);
        }
    }

    // Cayley-Menger determinant reduced exactly (two unit-pivot eliminations)
    // to a symmetric 4x4:  P[a][b] = D[a+1][b+1] - D[0][b+1] - D[0][a+1]
    // vol2 = PREFACTOR * det(CM) = det(P) / 9216.
    const float p00 = -2.0f * d2[pidx(0,1)];
    const float p11 = -2.0f * d2[pidx(0,2)];
    const float p22 = -2.0f * d2[pidx(0,3)];
    const float p33 = -2.0f * d2[pidx(0,4)];
    const float p01 = d2[pidx(1,2)] - d2[pidx(0,2)] - d2[pidx(0,1)];
    const float p02 = d2[pidx(1,3)] - d2[pidx(0,3)] - d2[pidx(0,1)];
    const float p03 = d2[pidx(1,4)] - d2[pidx(0,4)] - d2[pidx(0,1)];
    const float p12 = d2[pidx(2,3)] - d2[pidx(0,3)] - d2[pidx(0,2)];
    const float p13 = d2[pidx(2,4)] - d2[pidx(0,4)] - d2[pidx(0,2)];
    const float p23 = d2[pidx(3,4)] - d2[pidx(0,4)] - d2[pidx(0,3)];

    // det of symmetric 4x4 via 2x2 minors (rows 0,1 vs rows 2,3); c0 == s5.
    const float s0 = p00 * p11 - p01 * p01;
    const float s1 = p00 * p12 - p02 * p01;
    const float s2 = p00 * p13 - p03 * p01;
    const float s3 = p01 * p12 - p02 * p11;
    const float s4 = p01 * p13 - p03 * p11;
    const float s5 = p02 * p13 - p03 * p12;

    const float c1 = p02 * p23 - p22 * p03;
    const float c2 = p02 * p33 - p23 * p03;
    const float c3 = p12 * p23 - p22 * p13;
    const float c4 = p12 * p33 - p23 * p13;
    const float c5 = p22 * p33 - p23 * p23;

    const float det4 = s0 * c5 - s1 * c4 + s2 * c3 + s3 * c2 - s4 * c1 + s5 * s5;
    const float vol2 = det4 * (1.0f / 9216.0f);

    // Select this lane's pair value (lanes sub=0..7 own pairs 0..7; the
    // remaining two pairs are written by sub=0,1 at offset +8).
    float pv = d2[0];
    pv = (sub == 1) ? d2[1] : pv;
    pv = (sub == 2) ? d2[2] : pv;
    pv = (sub == 3) ? d2[3] : pv;
    pv = (sub == 4) ? d2[4] : pv;
    pv = (sub == 5) ? d2[5] : pv;
    pv = (sub == 6) ? d2[6] : pv;
    pv = (sub == 7) ? d2[7] : pv;
    float pv2 = (sub == 0) ? d2[8] : d2[9];

    float* op = out_pairs + (size_t)batch * 10;
    op[sub] = pv;
    if (sub < 2) {
        op[8 + sub] = pv2;
    }
    if (sub == 0) {
        out_vol[batch] = vol2;
    }
}

extern "C" void kernel_launch(void* const* d_in, const int* in_sizes, int n_in,
                              void* d_out, int out_size) {
    const float* verts = (const float*)d_in[0];
    const int B = in_sizes[0] / 640;   // (B, 5, 128) float32

    float* out = (float*)d_out;
    float* out_pairs = out;                      // (B, 10) flattened first
    float* out_vol   = out + (size_t)B * 10;     // (B,) concatenated after

    const int warps_needed = (B + 3) / 4;        // 4 batches per warp
    const int warps_per_block = 8;               // 256 threads
    const int blocks = (warps_needed + warps_per_block - 1) / warps_per_block;
    cm_validator_kernel<<<blocks, 256>>>(verts, out_pairs, out_vol, B);
}